// round 2
// baseline (speedup 1.0000x reference)
#include <cuda_runtime.h>
#include <cuda_bf16.h>
#include <cstdint>

#define BATCH 4
#define NN    4096
#define DIM   64
#define NROWS (BATCH * NN)   // 16384

// ---------------- device scratch (static allocation; no cudaMalloc) ----------------
__device__ __align__(16) __nv_bfloat16 g_ghat[(size_t)BATCH * NN * NN];   // 128 MB normalized adjacency, bf16
__device__ __align__(16) float         g_deg[NROWS];                      // d_i = 1/(sqrt(rowsum)+1e-7)
__device__ __align__(16) __nv_bfloat16 g_hbf[2][(size_t)NROWS * DIM];     // ping-pong bf16 h
__device__ __align__(16) float         g_hf[3][(size_t)NROWS * DIM];      // h1,h2,h3 fp32

// ---------------- helpers ----------------
__device__ __forceinline__ unsigned sptr(const void* p) {
    return (unsigned)__cvta_generic_to_shared(p);
}
__device__ __forceinline__ void cp_async16(void* dst, const void* src) {
    unsigned s = sptr(dst);
    asm volatile("cp.async.cg.shared.global [%0], [%1], 16;\n" :: "r"(s), "l"(src));
}

// ---------------- kernel 1: row degrees ----------------
// one warp per row; d = 1/(sqrt(sum_j g + 1) + 1e-7)
__global__ void __launch_bounds__(256) degree_kernel(const float* __restrict__ graph) {
    int row  = blockIdx.x * 8 + (threadIdx.x >> 5);
    int lane = threadIdx.x & 31;
    const float4* p = reinterpret_cast<const float4*>(graph + (size_t)row * NN);
    float s = 0.f;
    #pragma unroll 4
    for (int i = lane; i < NN / 4; i += 32) {
        float4 v = p[i];
        s += (v.x + v.y) + (v.z + v.w);
    }
    #pragma unroll
    for (int o = 16; o; o >>= 1) s += __shfl_xor_sync(0xffffffffu, s, o);
    if (lane == 0) g_deg[row] = 1.f / (sqrtf(s + 1.f) + 1e-7f);
}

// ---------------- kernel 2: build normalized adjacency in bf16 ----------------
__global__ void __launch_bounds__(256) build_kernel(const float* __restrict__ graph) {
    int row = blockIdx.y;                                  // 0..16383 (batch*4096 + i)
    int j0  = (blockIdx.x * blockDim.x + threadIdx.x) * 8; // 8 cols/thread
    int b   = row >> 12;
    int il  = row & (NN - 1);
    float di = g_deg[row];
    const float* src = graph + (size_t)row * NN + j0;
    float4 v0 = *(const float4*)(src);
    float4 v1 = *(const float4*)(src + 4);
    const float* djp = g_deg + b * NN + j0;
    float4 d0 = *(const float4*)(djp);
    float4 d1 = *(const float4*)(djp + 4);
    float a[8]  = {v0.x, v0.y, v0.z, v0.w, v1.x, v1.y, v1.z, v1.w};
    float dd[8] = {d0.x, d0.y, d0.z, d0.w, d1.x, d1.y, d1.z, d1.w};
    __nv_bfloat16 o[8];
    #pragma unroll
    for (int t = 0; t < 8; t++) {
        float g = a[t] + ((j0 + t) == il ? 1.f : 0.f);     // self loop
        o[t] = __float2bfloat16(g * di * dd[t]);
    }
    *(uint4*)(g_ghat + (size_t)row * NN + j0) = *(uint4*)o;
}

// ---------------- kernel 3: convert x to bf16 (h0 input for step 0) ----------------
__global__ void __launch_bounds__(256) xconv_kernel(const float* __restrict__ x) {
    int i = (blockIdx.x * blockDim.x + threadIdx.x) * 4;
    float4 v = *(const float4*)(x + i);
    __nv_bfloat162* o = (__nv_bfloat162*)(&g_hbf[0][i]);
    o[0] = __floats2bfloat162_rn(v.x, v.y);
    o[1] = __floats2bfloat162_rn(v.z, v.w);
}

// ---------------- kernel 4: propagation GEMM  C[4096,64] = Ghat[4096,4096] @ H[4096,64] ----------------
// CTA tile 64x64, KT=64, 4 warps (2x2 of 32x32), mma.sync m16n8k16 bf16, cp.async double buffer.
__global__ void __launch_bounds__(128) gemm_kernel(int step) {
    __shared__ __nv_bfloat16 As[2][64][72];   // +8 bf16 pad -> conflict-free ldmatrix
    __shared__ __nv_bfloat16 Bs[2][64][72];

    const int tid  = threadIdx.x;
    const int lane = tid & 31, wid = tid >> 5;
    const int wm = wid & 1, wn = wid >> 1;
    const size_t b = blockIdx.y;
    const int m0 = blockIdx.x * 64;

    const __nv_bfloat16* A   = g_ghat + b * ((size_t)NN * NN) + (size_t)m0 * NN;
    const __nv_bfloat16* Bin = g_hbf[step & 1] + b * ((size_t)NN * DIM);
    float*         Cf = g_hf[step] + b * ((size_t)NN * DIM);
    __nv_bfloat16* Cb = g_hbf[(step + 1) & 1] + b * ((size_t)NN * DIM);

    float acc[2][4][4];
    #pragma unroll
    for (int i = 0; i < 2; i++)
        #pragma unroll
        for (int j = 0; j < 4; j++)
            #pragma unroll
            for (int q = 0; q < 4; q++) acc[i][j][q] = 0.f;

    auto issue = [&](int kt, int bufi) {
        int kb = kt * 64;
        #pragma unroll
        for (int r = 0; r < 4; r++) {
            int idx = tid + r * 128;
            int row = idx >> 3, ch = idx & 7;
            cp_async16(&As[bufi][row][ch * 8], A + (size_t)row * NN + kb + ch * 8);
            cp_async16(&Bs[bufi][row][ch * 8], Bin + (size_t)(kb + row) * DIM + ch * 8);
        }
        asm volatile("cp.async.commit_group;\n" ::);
    };

    issue(0, 0);
    int buf = 0;
    const int lr = lane & 7, lq = (lane >> 3) & 1, lh = lane >> 4;

    for (int kt = 0; kt < NN / 64; kt++) {
        if (kt + 1 < NN / 64) {
            issue(kt + 1, buf ^ 1);
            asm volatile("cp.async.wait_group 1;\n" ::);
        } else {
            asm volatile("cp.async.wait_group 0;\n" ::);
        }
        __syncthreads();

        #pragma unroll
        for (int kk = 0; kk < 64; kk += 16) {
            uint32_t a[2][4];
            #pragma unroll
            for (int mt = 0; mt < 2; mt++) {
                unsigned p = sptr(&As[buf][wm * 32 + mt * 16 + lr + lq * 8][kk + lh * 8]);
                asm volatile("ldmatrix.sync.aligned.m8n8.x4.shared.b16 {%0,%1,%2,%3},[%4];\n"
                             : "=r"(a[mt][0]), "=r"(a[mt][1]), "=r"(a[mt][2]), "=r"(a[mt][3])
                             : "r"(p));
            }
            uint32_t bb[2][4];
            #pragma unroll
            for (int nh = 0; nh < 2; nh++) {
                unsigned p = sptr(&Bs[buf][kk + lr + lq * 8][wn * 32 + nh * 16 + lh * 8]);
                asm volatile("ldmatrix.sync.aligned.m8n8.x4.trans.shared.b16 {%0,%1,%2,%3},[%4];\n"
                             : "=r"(bb[nh][0]), "=r"(bb[nh][1]), "=r"(bb[nh][2]), "=r"(bb[nh][3])
                             : "r"(p));
            }
            #pragma unroll
            for (int mt = 0; mt < 2; mt++)
                #pragma unroll
                for (int nt = 0; nt < 4; nt++) {
                    uint32_t b0 = bb[nt >> 1][(nt & 1) * 2];
                    uint32_t b1 = bb[nt >> 1][(nt & 1) * 2 + 1];
                    float* c = acc[mt][nt];
                    asm volatile(
                        "mma.sync.aligned.m16n8k16.row.col.f32.bf16.bf16.f32 "
                        "{%0,%1,%2,%3},{%4,%5,%6,%7},{%8,%9},{%0,%1,%2,%3};\n"
                        : "+f"(c[0]), "+f"(c[1]), "+f"(c[2]), "+f"(c[3])
                        : "r"(a[mt][0]), "r"(a[mt][1]), "r"(a[mt][2]), "r"(a[mt][3]),
                          "r"(b0), "r"(b1));
                }
        }
        __syncthreads();
        buf ^= 1;
    }

    // epilogue: write fp32 h (for final linear) + bf16 h (for next step)
    #pragma unroll
    for (int mt = 0; mt < 2; mt++)
        #pragma unroll
        for (int nt = 0; nt < 4; nt++) {
            int r  = m0 + wm * 32 + mt * 16 + (lane >> 2);
            int cc = wn * 32 + nt * 8 + (lane & 3) * 2;
            float2 v01 = make_float2(acc[mt][nt][0], acc[mt][nt][1]);
            float2 v23 = make_float2(acc[mt][nt][2], acc[mt][nt][3]);
            *(float2*)(Cf + (size_t)r * DIM + cc)       = v01;
            *(float2*)(Cf + (size_t)(r + 8) * DIM + cc) = v23;
            *(__nv_bfloat162*)(Cb + (size_t)r * DIM + cc)       = __floats2bfloat162_rn(v01.x, v01.y);
            *(__nv_bfloat162*)(Cb + (size_t)(r + 8) * DIM + cc) = __floats2bfloat162_rn(v23.x, v23.y);
        }
}

// ---------------- kernel 5: out = [x,h1,h2,h3] @ W^T + b  (fp32, smem-tiled) ----------------
// 16 rows per block, 256 threads: tid&63 = output dim, tid>>6 = row group (4 rows each).
__global__ void __launch_bounds__(256) final_kernel(const float* __restrict__ x,
                                                    const float* __restrict__ W,
                                                    const float* __restrict__ bias,
                                                    float* __restrict__ out) {
    __shared__ float wt[128 * 64];    // W^T slice, [k_local][d]  (32 KB)
    __shared__ float cats[16 * 128];  // cat slice, [r][k_local]  (8 KB)

    const int tid = threadIdx.x;
    const int d   = tid & 63;
    const int rg  = tid >> 6;                 // 0..3, 4 rows each
    const int row0 = blockIdx.x * 16;

    float acc[4];
    float bv = bias[d];
    #pragma unroll
    for (int i = 0; i < 4; i++) acc[i] = bv;

    for (int half = 0; half < 2; half++) {
        for (int idx = tid; idx < 128 * 64; idx += 256) {
            int dd = idx >> 7;                // coalesced read along k
            int kl = idx & 127;
            wt[kl * 64 + dd] = W[dd * 256 + half * 128 + kl];
        }
        for (int idx = tid; idx < 16 * 128; idx += 256) {
            int r  = idx >> 7;
            int kl = idx & 127;
            int kg = half * 128 + kl;
            int seg = kg >> 6, kk = kg & 63;
            size_t ri = (size_t)(row0 + r) * DIM + kk;
            cats[idx] = (seg == 0) ? x[ri] : g_hf[seg - 1][ri];
        }
        __syncthreads();
        #pragma unroll 4
        for (int kl = 0; kl < 128; kl++) {
            float w = wt[kl * 64 + d];
            #pragma unroll
            for (int rr = 0; rr < 4; rr++)
                acc[rr] += cats[(rg * 4 + rr) * 128 + kl] * w;
        }
        __syncthreads();
    }
    #pragma unroll
    for (int rr = 0; rr < 4; rr++)
        out[(size_t)(row0 + rg * 4 + rr) * DIM + d] = acc[rr];
}

// ---------------- launch ----------------
extern "C" void kernel_launch(void* const* d_in, const int* in_sizes, int n_in,
                              void* d_out, int out_size) {
    const float* x     = (const float*)d_in[0];   // [4,4096,64]
    const float* graph = (const float*)d_in[1];   // [4,4096,4096]
    const float* W     = (const float*)d_in[2];   // [64,256]
    const float* bias  = (const float*)d_in[3];   // [64]
    float* out = (float*)d_out;                   // [4,4096,64]

    degree_kernel<<<NROWS / 8, 256>>>(graph);
    build_kernel<<<dim3(2, NROWS), 256>>>(graph);
    xconv_kernel<<<(NROWS * DIM) / (256 * 4), 256>>>(x);
    for (int s = 0; s < 3; s++)
        gemm_kernel<<<dim3(NN / 64, BATCH), 128>>>(s);
    final_kernel<<<NROWS / 16, 256>>>(x, W, bias, out);
}

// round 3
// speedup vs baseline: 1.1460x; 1.1460x over previous
#include <cuda_runtime.h>
#include <cuda_bf16.h>
#include <cstdint>

#define BATCH 4
#define NN    4096
#define DIM   64
#define NROWS (BATCH * NN)   // 16384

#define STAGES 5
#define PADW   72            // 64 + 8 bf16 pad (row = 144B = 9*16B, conflict-free)

// ---------------- device scratch (static; no cudaMalloc) ----------------
__device__ __align__(16) __nv_bfloat16 g_ghat[(size_t)BATCH * NN * NN];   // 128 MB bf16 normalized adjacency
__device__ __align__(16) float         g_deg[NROWS];
__device__ __align__(16) float         g_P[4][(size_t)NROWS * DIM];       // P_k = x @ W_k^T (fp32)
__device__ __align__(16) __nv_bfloat16 g_sbf[2][(size_t)NROWS * DIM];     // ping-pong bf16 state

// ---------------- helpers ----------------
__device__ __forceinline__ unsigned sptr(const void* p) {
    return (unsigned)__cvta_generic_to_shared(p);
}
__device__ __forceinline__ void cp_async16(void* dst, const void* src) {
    asm volatile("cp.async.cg.shared.global [%0], [%1], 16;\n" :: "r"(sptr(dst)), "l"(src));
}

// ---------------- kernel 1: row degrees ----------------
__global__ void __launch_bounds__(256) degree_kernel(const float* __restrict__ graph) {
    int row  = blockIdx.x * 8 + (threadIdx.x >> 5);
    int lane = threadIdx.x & 31;
    const float4* p = reinterpret_cast<const float4*>(graph + (size_t)row * NN);
    float s = 0.f;
    #pragma unroll 4
    for (int i = lane; i < NN / 4; i += 32) {
        float4 v = p[i];
        s += (v.x + v.y) + (v.z + v.w);
    }
    #pragma unroll
    for (int o = 16; o; o >>= 1) s += __shfl_xor_sync(0xffffffffu, s, o);
    if (lane == 0) g_deg[row] = 1.f / (sqrtf(s + 1.f) + 1e-7f);
}

// ---------------- kernel 2: build normalized adjacency (bf16) ----------------
__global__ void __launch_bounds__(256) build_kernel(const float* __restrict__ graph) {
    int row = blockIdx.y;
    int j0  = (blockIdx.x * blockDim.x + threadIdx.x) * 8;
    int b   = row >> 12;
    int il  = row & (NN - 1);
    float di = g_deg[row];
    const float* src = graph + (size_t)row * NN + j0;
    float4 v0 = *(const float4*)(src);
    float4 v1 = *(const float4*)(src + 4);
    const float* djp = g_deg + b * NN + j0;
    float4 d0 = *(const float4*)(djp);
    float4 d1 = *(const float4*)(djp + 4);
    float a[8]  = {v0.x, v0.y, v0.z, v0.w, v1.x, v1.y, v1.z, v1.w};
    float dd[8] = {d0.x, d0.y, d0.z, d0.w, d1.x, d1.y, d1.z, d1.w};
    __nv_bfloat16 o[8];
    #pragma unroll
    for (int t = 0; t < 8; t++) {
        float g = a[t] + ((j0 + t) == il ? 1.f : 0.f);
        o[t] = __float2bfloat16(g * di * dd[t]);
    }
    *(uint4*)(g_ghat + (size_t)row * NN + j0) = *(uint4*)o;
}

// ---------------- kernel 3: P_k = x @ W_k^T (fp32), seed s0 = bf16(P_3) ----------------
// 256 threads: (d = tid&63, kseg = tid>>6). 64 rows per block.
__global__ void __launch_bounds__(256) precompute_kernel(const float* __restrict__ x,
                                                         const float* __restrict__ W) {
    __shared__ float xs[64][65];
    const int tid  = threadIdx.x;
    const int d    = tid & 63;
    const int kseg = tid >> 6;
    const int row0 = blockIdx.x * 64;

    float wreg[64];
    const float4* wp = (const float4*)(W + d * 256 + kseg * 64);
    #pragma unroll
    for (int i = 0; i < 16; i++) {
        float4 v = wp[i];
        wreg[i*4+0] = v.x; wreg[i*4+1] = v.y; wreg[i*4+2] = v.z; wreg[i*4+3] = v.w;
    }
    for (int idx = tid; idx < 64 * 64; idx += 256) {
        int r = idx >> 6, c = idx & 63;
        xs[r][c] = x[(size_t)(row0 + r) * DIM + c];
    }
    __syncthreads();

    for (int r = 0; r < 64; r++) {
        float a0 = 0.f, a1 = 0.f;
        #pragma unroll
        for (int c = 0; c < 64; c += 2) {
            a0 += xs[r][c]     * wreg[c];
            a1 += xs[r][c + 1] * wreg[c + 1];
        }
        float acc = a0 + a1;
        size_t gi = (size_t)(row0 + r) * DIM + d;
        g_P[kseg][gi] = acc;
        if (kseg == 3) g_sbf[0][gi] = __float2bfloat16(acc);
    }
}

// ---------------- kernel 4: S_out = ghat @ S_in + P  (last step: out = ... + bias, fp32) ----------------
// CTA tile 64x64, 8 warps (4x2: warp tile m16 x n32), K chunk 64, 5-stage cp.async pipeline.
__global__ void __launch_bounds__(256) gemm_kernel(const __nv_bfloat16* __restrict__ Sin,
                                                   __nv_bfloat16* __restrict__ Sout,
                                                   const float* __restrict__ Padd,
                                                   float* __restrict__ outp,      // null unless last step
                                                   const float* __restrict__ bias) {
    extern __shared__ __nv_bfloat16 smem[];
    __nv_bfloat16* Asm = smem;                               // [STAGES][64][PADW]
    __nv_bfloat16* Bsm = smem + STAGES * 64 * PADW;

    const int tid = threadIdx.x, lane = tid & 31, wid = tid >> 5;
    const int wm = wid & 3, wn = wid >> 2;
    const size_t b = blockIdx.y;
    const int m0 = blockIdx.x * 64;

    const __nv_bfloat16* A = g_ghat + b * ((size_t)NN * NN) + (size_t)m0 * NN;
    const __nv_bfloat16* B = Sin + b * ((size_t)NN * DIM);

    float acc[4][4];
    #pragma unroll
    for (int i = 0; i < 4; i++)
        #pragma unroll
        for (int j = 0; j < 4; j++) acc[i][j] = 0.f;

    auto issue = [&](int kt) {
        if (kt < NN / 64) {
            int st = kt % STAGES;
            int kb = kt * 64;
            __nv_bfloat16* a  = Asm + st * 64 * PADW;
            __nv_bfloat16* bs = Bsm + st * 64 * PADW;
            #pragma unroll
            for (int r = 0; r < 2; r++) {
                int idx = tid + r * 256;
                int row = idx >> 3, ch = idx & 7;
                cp_async16(a  + row * PADW + ch * 8, A + (size_t)row * NN + kb + ch * 8);
                cp_async16(bs + row * PADW + ch * 8, B + (size_t)(kb + row) * DIM + ch * 8);
            }
        }
        asm volatile("cp.async.commit_group;\n" ::);   // empty group at tail keeps wait_group semantics
    };

    #pragma unroll
    for (int kt = 0; kt < STAGES - 1; kt++) issue(kt);

    const int la = lane & 15, lb = lane >> 4;

    for (int kt = 0; kt < NN / 64; kt++) {
        asm volatile("cp.async.wait_group %0;\n" :: "n"(STAGES - 2));
        __syncthreads();
        const __nv_bfloat16* a  = Asm + (kt % STAGES) * 64 * PADW;
        const __nv_bfloat16* bs = Bsm + (kt % STAGES) * 64 * PADW;

        #pragma unroll
        for (int kk = 0; kk < 64; kk += 16) {
            uint32_t af[4];
            {
                unsigned p = sptr(a + (wm * 16 + la) * PADW + kk + lb * 8);
                asm volatile("ldmatrix.sync.aligned.m8n8.x4.shared.b16 {%0,%1,%2,%3},[%4];\n"
                             : "=r"(af[0]), "=r"(af[1]), "=r"(af[2]), "=r"(af[3]) : "r"(p));
            }
            uint32_t bf_[2][4];
            #pragma unroll
            for (int nh = 0; nh < 2; nh++) {
                unsigned p = sptr(bs + (kk + la) * PADW + wn * 32 + nh * 16 + lb * 8);
                asm volatile("ldmatrix.sync.aligned.m8n8.x4.trans.shared.b16 {%0,%1,%2,%3},[%4];\n"
                             : "=r"(bf_[nh][0]), "=r"(bf_[nh][1]), "=r"(bf_[nh][2]), "=r"(bf_[nh][3])
                             : "r"(p));
            }
            #pragma unroll
            for (int nt = 0; nt < 4; nt++) {
                uint32_t b0 = bf_[nt >> 1][(nt & 1) * 2];
                uint32_t b1 = bf_[nt >> 1][(nt & 1) * 2 + 1];
                float* c = acc[nt];
                asm volatile(
                    "mma.sync.aligned.m16n8k16.row.col.f32.bf16.bf16.f32 "
                    "{%0,%1,%2,%3},{%4,%5,%6,%7},{%8,%9},{%0,%1,%2,%3};\n"
                    : "+f"(c[0]), "+f"(c[1]), "+f"(c[2]), "+f"(c[3])
                    : "r"(af[0]), "r"(af[1]), "r"(af[2]), "r"(af[3]), "r"(b0), "r"(b1));
            }
        }
        issue(kt + STAGES - 1);
    }

    // epilogue: acc += P (fp32); last step adds bias -> fp32 out, else bf16 state
    const int rloc = wm * 16 + (lane >> 2);
    const size_t gr = b * NN + m0 + rloc;
    #pragma unroll
    for (int nt = 0; nt < 4; nt++) {
        int c = wn * 32 + nt * 8 + (lane & 3) * 2;
        float2 p0 = *(const float2*)(Padd + gr * DIM + c);
        float2 p1 = *(const float2*)(Padd + (gr + 8) * DIM + c);
        float v0 = acc[nt][0] + p0.x, v1 = acc[nt][1] + p0.y;
        float v2 = acc[nt][2] + p1.x, v3 = acc[nt][3] + p1.y;
        if (outp) {
            float b0 = bias[c], b1 = bias[c + 1];
            *(float2*)(outp + gr * DIM + c)       = make_float2(v0 + b0, v1 + b1);
            *(float2*)(outp + (gr + 8) * DIM + c) = make_float2(v2 + b0, v3 + b1);
        } else {
            *(__nv_bfloat162*)(Sout + gr * DIM + c)       = __floats2bfloat162_rn(v0, v1);
            *(__nv_bfloat162*)(Sout + (gr + 8) * DIM + c) = __floats2bfloat162_rn(v2, v3);
        }
    }
}

// ---------------- launch ----------------
extern "C" void kernel_launch(void* const* d_in, const int* in_sizes, int n_in,
                              void* d_out, int out_size) {
    const float* x     = (const float*)d_in[0];   // [4,4096,64]
    const float* graph = (const float*)d_in[1];   // [4,4096,4096]
    const float* W     = (const float*)d_in[2];   // [64,256]
    const float* bias  = (const float*)d_in[3];   // [64]
    float* out = (float*)d_out;                   // [4,4096,64]

    const int smem_bytes = STAGES * 64 * PADW * 2 /*bf16*/ * 2 /*A+B*/;   // 92160
    static bool attr_set = false;   // attribute is persistent process state, not a work guard
    if (!attr_set) {
        cudaFuncSetAttribute(gemm_kernel, cudaFuncAttributeMaxDynamicSharedMemorySize, smem_bytes);
        attr_set = true;
    }

    degree_kernel<<<NROWS / 8, 256>>>(graph);
    build_kernel<<<dim3(2, NROWS), 256>>>(graph);
    precompute_kernel<<<NROWS / 64, 256>>>(x, W);

    __nv_bfloat16* s0 = nullptr; __nv_bfloat16* s1 = nullptr;
    cudaGetSymbolAddress((void**)&s0, g_sbf);      // g_sbf[0]
    s1 = s0 + (size_t)NROWS * DIM;                 // g_sbf[1]
    float* P = nullptr;
    cudaGetSymbolAddress((void**)&P, g_P);         // g_P[0]

    dim3 grid(NN / 64, BATCH);
    // step 0: s1 = ghat @ s0 + P2
    gemm_kernel<<<grid, 256, smem_bytes>>>(s0, s1, P + 2 * (size_t)NROWS * DIM, nullptr, bias);
    // step 1: s0 = ghat @ s1 + P1
    gemm_kernel<<<grid, 256, smem_bytes>>>(s1, s0, P + 1 * (size_t)NROWS * DIM, nullptr, bias);
    // step 2: out = ghat @ s0 + P0 + bias
    gemm_kernel<<<grid, 256, smem_bytes>>>(s0, s1, P, out, bias);
}

// round 4
// speedup vs baseline: 1.4224x; 1.2412x over previous
#include <cuda_runtime.h>
#include <cuda_bf16.h>
#include <cstdint>

#define BATCH 4
#define NN    4096
#define DIM   64
#define NROWS (BATCH * NN)   // 16384

#define STAGES 4
#define PADW   72            // 64 + 8 bf16 pad (row = 144B, conflict-free ldmatrix)

// ---------------- device scratch (static; no cudaMalloc) ----------------
__device__ __align__(16) __nv_bfloat16 g_A[(size_t)BATCH * NN * NN];      // 128 MB bf16 (g + I), UNnormalized
__device__ __align__(16) float         g_deg[NROWS];                      // d_i = 1/(sqrt(rowsum)+1e-7)
__device__ __align__(16) float         g_P[4][(size_t)NROWS * DIM];       // P_k = x @ W_k^T (fp32)
__device__ __align__(16) __nv_bfloat16 g_sbf[2][(size_t)NROWS * DIM];     // ping-pong bf16 state T = D*S

// ---------------- helpers ----------------
__device__ __forceinline__ unsigned sptr(const void* p) {
    return (unsigned)__cvta_generic_to_shared(p);
}
__device__ __forceinline__ void cp_async16(void* dst, const void* src) {
    asm volatile("cp.async.cg.shared.global [%0], [%1], 16;\n" :: "r"(sptr(dst)), "l"(src));
}

// ---------------- kernel 1: fused degree + bf16(g+I) build, single pass ----------------
// one warp per row: read fp32 row once, add self-loop, accumulate row sum, write bf16.
__global__ void __launch_bounds__(256) prep_kernel(const float* __restrict__ graph) {
    int row  = blockIdx.x * 8 + (threadIdx.x >> 5);
    int lane = threadIdx.x & 31;
    int il   = row & (NN - 1);                     // diagonal index within row
    const float4* p = reinterpret_cast<const float4*>(graph + (size_t)row * NN);
    __nv_bfloat16* dst = g_A + (size_t)row * NN;

    float s = 0.f;
    #pragma unroll 4
    for (int i = lane; i < NN / 4; i += 32) {
        float4 v = p[i];
        int j0 = i * 4;
        if (il - j0 >= 0 && il - j0 < 4) reinterpret_cast<float*>(&v)[il - j0] += 1.f;  // self loop
        s += (v.x + v.y) + (v.z + v.w);
        __nv_bfloat16 o[4] = {__float2bfloat16(v.x), __float2bfloat16(v.y),
                              __float2bfloat16(v.z), __float2bfloat16(v.w)};
        *reinterpret_cast<uint2*>(dst + j0) = *reinterpret_cast<uint2*>(o);
    }
    #pragma unroll
    for (int o = 16; o; o >>= 1) s += __shfl_xor_sync(0xffffffffu, s, o);
    if (lane == 0) g_deg[row] = 1.f / (sqrtf(s) + 1e-7f);   // s already includes +1
}

// ---------------- kernel 2: P_k = x @ W_k^T (fp32), seed T0 = bf16(d * P3) ----------------
__global__ void __launch_bounds__(256) precompute_kernel(const float* __restrict__ x,
                                                         const float* __restrict__ W) {
    __shared__ float xs[64][65];
    const int tid  = threadIdx.x;
    const int d    = tid & 63;
    const int kseg = tid >> 6;
    const int row0 = blockIdx.x * 64;

    float wreg[64];
    const float4* wp = (const float4*)(W + d * 256 + kseg * 64);
    #pragma unroll
    for (int i = 0; i < 16; i++) {
        float4 v = wp[i];
        wreg[i*4+0] = v.x; wreg[i*4+1] = v.y; wreg[i*4+2] = v.z; wreg[i*4+3] = v.w;
    }
    for (int idx = tid; idx < 64 * 64; idx += 256) {
        int r = idx >> 6, c = idx & 63;
        xs[r][c] = x[(size_t)(row0 + r) * DIM + c];
    }
    __syncthreads();

    for (int r = 0; r < 64; r++) {
        float a0 = 0.f, a1 = 0.f;
        #pragma unroll
        for (int c = 0; c < 64; c += 2) {
            a0 += xs[r][c]     * wreg[c];
            a1 += xs[r][c + 1] * wreg[c + 1];
        }
        float acc = a0 + a1;
        size_t gi = (size_t)(row0 + r) * DIM + d;
        g_P[kseg][gi] = acc;
        if (kseg == 3) g_sbf[0][gi] = __float2bfloat16(acc * g_deg[row0 + r]);
    }
}

// ---------------- kernel 3: acc = A @ T ; epilogue applies D factors + P (+bias) ----------------
// CTA tile 64x64, 4 warps of m32xn32 (2x2 grid), K chunk 64, 4-stage cp.async pipeline.
__global__ void __launch_bounds__(128) gemm_kernel(const __nv_bfloat16* __restrict__ Tin,
                                                   __nv_bfloat16* __restrict__ Tout,
                                                   const float* __restrict__ Padd,
                                                   float* __restrict__ outp,      // null unless last step
                                                   const float* __restrict__ bias) {
    extern __shared__ __nv_bfloat16 smem[];
    __nv_bfloat16* Asm = smem;                               // [STAGES][64][PADW]
    __nv_bfloat16* Bsm = smem + STAGES * 64 * PADW;

    const int tid = threadIdx.x, lane = tid & 31, wid = tid >> 5;
    const int wm = wid & 1, wn = wid >> 1;
    const size_t b = blockIdx.y;
    const int m0 = blockIdx.x * 64;

    const __nv_bfloat16* A = g_A + b * ((size_t)NN * NN) + (size_t)m0 * NN;
    const __nv_bfloat16* B = Tin + b * ((size_t)NN * DIM);

    float acc[2][4][4];
    #pragma unroll
    for (int i = 0; i < 2; i++)
        #pragma unroll
        for (int j = 0; j < 4; j++)
            #pragma unroll
            for (int q = 0; q < 4; q++) acc[i][j][q] = 0.f;

    auto issue = [&](int kt) {
        if (kt < NN / 64) {
            int st = kt % STAGES;
            int kb = kt * 64;
            __nv_bfloat16* a  = Asm + st * 64 * PADW;
            __nv_bfloat16* bs = Bsm + st * 64 * PADW;
            #pragma unroll
            for (int r = 0; r < 4; r++) {
                int idx = tid + r * 128;
                int row = idx >> 3, ch = idx & 7;
                cp_async16(a  + row * PADW + ch * 8, A + (size_t)row * NN + kb + ch * 8);
                cp_async16(bs + row * PADW + ch * 8, B + (size_t)(kb + row) * DIM + ch * 8);
            }
        }
        asm volatile("cp.async.commit_group;\n" ::);   // empty group at tail keeps wait_group semantics
    };

    #pragma unroll
    for (int kt = 0; kt < STAGES - 1; kt++) issue(kt);

    const int la = lane & 15, lb = lane >> 4;

    for (int kt = 0; kt < NN / 64; kt++) {
        asm volatile("cp.async.wait_group %0;\n" :: "n"(STAGES - 2));
        __syncthreads();
        const __nv_bfloat16* a  = Asm + (kt % STAGES) * 64 * PADW;
        const __nv_bfloat16* bs = Bsm + (kt % STAGES) * 64 * PADW;

        #pragma unroll
        for (int kk = 0; kk < 64; kk += 16) {
            uint32_t af[2][4];
            #pragma unroll
            for (int mt = 0; mt < 2; mt++) {
                unsigned p = sptr(a + (wm * 32 + mt * 16 + la) * PADW + kk + lb * 8);
                asm volatile("ldmatrix.sync.aligned.m8n8.x4.shared.b16 {%0,%1,%2,%3},[%4];\n"
                             : "=r"(af[mt][0]), "=r"(af[mt][1]), "=r"(af[mt][2]), "=r"(af[mt][3])
                             : "r"(p));
            }
            uint32_t bf_[2][4];
            #pragma unroll
            for (int nh = 0; nh < 2; nh++) {
                unsigned p = sptr(bs + (kk + la) * PADW + wn * 32 + nh * 16 + lb * 8);
                asm volatile("ldmatrix.sync.aligned.m8n8.x4.trans.shared.b16 {%0,%1,%2,%3},[%4];\n"
                             : "=r"(bf_[nh][0]), "=r"(bf_[nh][1]), "=r"(bf_[nh][2]), "=r"(bf_[nh][3])
                             : "r"(p));
            }
            #pragma unroll
            for (int mt = 0; mt < 2; mt++)
                #pragma unroll
                for (int nt = 0; nt < 4; nt++) {
                    uint32_t b0 = bf_[nt >> 1][(nt & 1) * 2];
                    uint32_t b1 = bf_[nt >> 1][(nt & 1) * 2 + 1];
                    float* c = acc[mt][nt];
                    asm volatile(
                        "mma.sync.aligned.m16n8k16.row.col.f32.bf16.bf16.f32 "
                        "{%0,%1,%2,%3},{%4,%5,%6,%7},{%8,%9},{%0,%1,%2,%3};\n"
                        : "+f"(c[0]), "+f"(c[1]), "+f"(c[2]), "+f"(c[3])
                        : "r"(af[mt][0]), "r"(af[mt][1]), "r"(af[mt][2]), "r"(af[mt][3]),
                          "r"(b0), "r"(b1));
                }
        }
        issue(kt + STAGES - 1);
    }

    // epilogue: S_next[r] = d_r*acc + P[r]; state out T_next = bf16(d_r * S_next)
    #pragma unroll
    for (int mt = 0; mt < 2; mt++) {
        const size_t gr0 = b * NN + m0 + wm * 32 + mt * 16 + (lane >> 2);
        const size_t gr1 = gr0 + 8;
        const float d0 = g_deg[gr0], d1 = g_deg[gr1];
        #pragma unroll
        for (int nt = 0; nt < 4; nt++) {
            int c = wn * 32 + nt * 8 + (lane & 3) * 2;
            float2 p0 = *(const float2*)(Padd + gr0 * DIM + c);
            float2 p1 = *(const float2*)(Padd + gr1 * DIM + c);
            float* ac = acc[mt][nt];
            float s00 = d0 * ac[0] + p0.x, s01 = d0 * ac[1] + p0.y;
            float s10 = d1 * ac[2] + p1.x, s11 = d1 * ac[3] + p1.y;
            if (outp) {
                float b0 = bias[c], b1 = bias[c + 1];
                *(float2*)(outp + gr0 * DIM + c) = make_float2(s00 + b0, s01 + b1);
                *(float2*)(outp + gr1 * DIM + c) = make_float2(s10 + b0, s11 + b1);
            } else {
                *(__nv_bfloat162*)(Tout + gr0 * DIM + c) = __floats2bfloat162_rn(d0 * s00, d0 * s01);
                *(__nv_bfloat162*)(Tout + gr1 * DIM + c) = __floats2bfloat162_rn(d1 * s10, d1 * s11);
            }
        }
    }
}

// ---------------- launch ----------------
extern "C" void kernel_launch(void* const* d_in, const int* in_sizes, int n_in,
                              void* d_out, int out_size) {
    const float* x     = (const float*)d_in[0];   // [4,4096,64]
    const float* graph = (const float*)d_in[1];   // [4,4096,4096]
    const float* W     = (const float*)d_in[2];   // [64,256]
    const float* bias  = (const float*)d_in[3];   // [64]
    float* out = (float*)d_out;                   // [4,4096,64]

    const int smem_bytes = STAGES * 64 * PADW * 2 /*bf16*/ * 2 /*A+B*/;   // 73728
    static bool attr_set = false;   // persistent process state, not a work guard
    if (!attr_set) {
        cudaFuncSetAttribute(gemm_kernel, cudaFuncAttributeMaxDynamicSharedMemorySize, smem_bytes);
        attr_set = true;
    }

    prep_kernel<<<NROWS / 8, 256>>>(graph);
    precompute_kernel<<<NROWS / 64, 256>>>(x, W);

    __nv_bfloat16* s0 = nullptr;
    cudaGetSymbolAddress((void**)&s0, g_sbf);      // g_sbf[0]
    __nv_bfloat16* s1 = s0 + (size_t)NROWS * DIM;  // g_sbf[1]
    float* P = nullptr;
    cudaGetSymbolAddress((void**)&P, g_P);         // g_P[0]

    dim3 grid(NN / 64, BATCH);
    // step 0: T1 <- d*(d*(A@T0) + P2)
    gemm_kernel<<<grid, 128, smem_bytes>>>(s0, s1, P + 2 * (size_t)NROWS * DIM, nullptr, bias);
    // step 1: T0 <- d*(d*(A@T1) + P1)
    gemm_kernel<<<grid, 128, smem_bytes>>>(s1, s0, P + 1 * (size_t)NROWS * DIM, nullptr, bias);
    // step 2: out = d*(A@T0) + P0 + bias
    gemm_kernel<<<grid, 128, smem_bytes>>>(s0, s1, P, out, bias);
}

// round 8
// speedup vs baseline: 1.4306x; 1.0058x over previous
#include <cuda_runtime.h>
#include <cuda_bf16.h>
#include <cstdint>

#define BATCH 4
#define NN    4096
#define DIM   64
#define NROWS (BATCH * NN)   // 16384

#define STAGES   5
#define KT_TOT   (NN / 64)           // 64 K-chunks of 64
#define ROWB     144                 // 72 bf16 padded row = 144 B (conflict-free ldmatrix)
#define A_STG    (64 * ROWB)         // 9216 B
#define B_STG    (64 * ROWB)         // 9216 B
#define STG      (A_STG + B_STG)     // 18432 B

// ---------------- device scratch (static; no cudaMalloc) ----------------
__device__ __align__(16) __nv_bfloat16 g_A[(size_t)BATCH * NN * NN];   // 128 MB bf16 (g+I)
__device__ __align__(16) float         g_deg[NROWS];
__device__ __align__(16) float         g_P[4][(size_t)NROWS * DIM];    // P_k = x @ W_k^T
__device__ __align__(16) __nv_bfloat16 g_sbf[2][(size_t)NROWS * DIM];  // ping-pong bf16 state T = D*S

// ---------------- asm helpers (all base-ISA: sm_80/sm_90, OK under compute_103) ----------------
__device__ __forceinline__ void cp_async16_s(uint32_t dst, const void* src) {
    asm volatile("cp.async.cg.shared.global [%0], [%1], 16;\n" :: "r"(dst), "l"(src));
}
__device__ __forceinline__ void mbar_init(uint32_t a, uint32_t cnt) {
    asm volatile("mbarrier.init.shared.b64 [%0], %1;\n" :: "r"(a), "r"(cnt) : "memory");
}
__device__ __forceinline__ void mbar_arrive(uint32_t a) {
    asm volatile("mbarrier.arrive.shared.b64 _, [%0];\n" :: "r"(a) : "memory");
}
__device__ __forceinline__ void cp_arrive_noinc(uint32_t a) {
    asm volatile("cp.async.mbarrier.arrive.noinc.shared.b64 [%0];\n" :: "r"(a) : "memory");
}
__device__ __forceinline__ void mbar_wait(uint32_t a, uint32_t parity) {
    asm volatile(
        "{\n\t.reg .pred P1;\n\t"
        "WAIT_%=:\n\t"
        "mbarrier.try_wait.parity.acquire.cta.shared::cta.b64 P1, [%0], %1, 0x989680;\n\t"
        "@P1 bra.uni DONE_%=;\n\t"
        "bra.uni WAIT_%=;\n\t"
        "DONE_%=:\n\t}"
        :: "r"(a), "r"(parity) : "memory");
}

// ---------------- kernel 1: fused degree + bf16(g+I), single pass, high MLP ----------------
__global__ void __launch_bounds__(256) prep_kernel(const float* __restrict__ graph) {
    int row  = blockIdx.x * 8 + (threadIdx.x >> 5);
    int lane = threadIdx.x & 31;
    int il   = row & (NN - 1);
    const float4* p = reinterpret_cast<const float4*>(graph + (size_t)row * NN);
    __nv_bfloat16* dst = g_A + (size_t)row * NN;

    float s = 0.f;
    #pragma unroll 4
    for (int i = lane; i < NN / 8; i += 32) {
        float4 v0 = p[2 * i];
        float4 v1 = p[2 * i + 1];
        int j0 = i * 8;
        int dsl = il - j0;
        if (dsl >= 0 && dsl < 8) {                       // self loop
            float* vv = (dsl < 4) ? reinterpret_cast<float*>(&v0) : reinterpret_cast<float*>(&v1);
            vv[dsl & 3] += 1.f;
        }
        s += ((v0.x + v0.y) + (v0.z + v0.w)) + ((v1.x + v1.y) + (v1.z + v1.w));
        __nv_bfloat16 o[8] = {__float2bfloat16(v0.x), __float2bfloat16(v0.y),
                              __float2bfloat16(v0.z), __float2bfloat16(v0.w),
                              __float2bfloat16(v1.x), __float2bfloat16(v1.y),
                              __float2bfloat16(v1.z), __float2bfloat16(v1.w)};
        *reinterpret_cast<uint4*>(dst + j0) = *reinterpret_cast<uint4*>(o);
    }
    #pragma unroll
    for (int o = 16; o; o >>= 1) s += __shfl_xor_sync(0xffffffffu, s, o);
    if (lane == 0) g_deg[row] = 1.f / (sqrtf(s) + 1e-7f);
}

// ---------------- kernel 2: P_k = x @ W_k^T, seed T0 = bf16(d * P3) ----------------
__global__ void __launch_bounds__(256) precompute_kernel(const float* __restrict__ x,
                                                         const float* __restrict__ W) {
    __shared__ float xs[64][65];
    const int tid  = threadIdx.x;
    const int d    = tid & 63;
    const int kseg = tid >> 6;
    const int row0 = blockIdx.x * 64;

    float wreg[64];
    const float4* wp = (const float4*)(W + d * 256 + kseg * 64);
    #pragma unroll
    for (int i = 0; i < 16; i++) {
        float4 v = wp[i];
        wreg[i*4+0] = v.x; wreg[i*4+1] = v.y; wreg[i*4+2] = v.z; wreg[i*4+3] = v.w;
    }
    for (int idx = tid; idx < 64 * 64; idx += 256) {
        int r = idx >> 6, c = idx & 63;
        xs[r][c] = x[(size_t)(row0 + r) * DIM + c];
    }
    __syncthreads();

    for (int r = 0; r < 64; r++) {
        float a0 = 0.f, a1 = 0.f;
        #pragma unroll
        for (int c = 0; c < 64; c += 2) {
            a0 += xs[r][c]     * wreg[c];
            a1 += xs[r][c + 1] * wreg[c + 1];
        }
        float acc = a0 + a1;
        size_t gi = (size_t)(row0 + r) * DIM + d;
        g_P[kseg][gi] = acc;
        if (kseg == 3) g_sbf[0][gi] = __float2bfloat16(acc * g_deg[row0 + r]);
    }
}

// ---------------- kernel 3: warp-specialized mma.sync GEMM ----------------
// CTA tile 64x64. Warps 0-3: consumers (32x32 warp tiles, ldmatrix + mma.sync).
// Warps 4-7: producers (cp.async -> 5-stage ring, cp.async.mbarrier.arrive.noinc).
__global__ void __launch_bounds__(256) gemm_kernel(const __nv_bfloat16* __restrict__ Tin,
                                                   __nv_bfloat16* __restrict__ Tout,
                                                   const float* __restrict__ Padd,
                                                   float* __restrict__ outp,   // null unless last step
                                                   const float* __restrict__ bias) {
    extern __shared__ char smem_raw[];
    const uint32_t base = (uint32_t)__cvta_generic_to_shared(smem_raw);  // 16B-aligned; ROWB=144 keeps 16B chunks aligned
    const uint32_t barb = base + STAGES * STG;     // full[s] @ barb+16s, empty[s] @ barb+16s+8

    const int tid = threadIdx.x, lane = tid & 31, wid = tid >> 5;
    const size_t b = blockIdx.y;
    const int m0 = blockIdx.x * 64;

    const __nv_bfloat16* A = g_A + b * ((size_t)NN * NN) + (size_t)m0 * NN;
    const __nv_bfloat16* B = Tin + b * ((size_t)NN * DIM);

    if (tid == 0) {
        #pragma unroll
        for (int s = 0; s < STAGES; s++) {
            mbar_init(barb + 16 * s, 128);         // full: 128 producer threads
            mbar_init(barb + 16 * s + 8, 128);     // empty: 128 consumer threads
        }
    }
    __syncthreads();

    if (wid >= 4) {
        // ================= producers =================
        const int ptid = tid - 128;                // 0..127
        int st_i = 0, ph = 1;                      // empty-wait cursor (phase 1: first pass free)
        for (int kt = 0; kt < KT_TOT; kt++) {
            mbar_wait(barb + 16 * st_i + 8, (uint32_t)ph);
            const uint32_t st = base + st_i * STG;
            const int kb = kt * 64;
            #pragma unroll
            for (int i = 0; i < 4; i++) {          // A: 512 chunks of 16B
                int idx = ptid + i * 128;
                int r = idx >> 3, c = idx & 7;
                cp_async16_s(st + r * ROWB + c * 16, A + (size_t)r * NN + kb + c * 8);
            }
            #pragma unroll
            for (int i = 0; i < 4; i++) {          // B: 512 chunks of 16B
                int idx = ptid + i * 128;
                int r = idx >> 3, c = idx & 7;
                cp_async16_s(st + A_STG + r * ROWB + c * 16, B + (size_t)(kb + r) * DIM + c * 8);
            }
            cp_arrive_noinc(barb + 16 * st_i);     // arrive full[s] when this thread's cp.asyncs land
            if (++st_i == STAGES) { st_i = 0; ph ^= 1; }
        }
        return;
    }

    // ================= consumers =================
    const int wm = wid & 1, wn = wid >> 1;
    const int la = lane & 15, lb = lane >> 4;

    float acc[2][4][4];
    #pragma unroll
    for (int i = 0; i < 2; i++)
        #pragma unroll
        for (int j = 0; j < 4; j++)
            #pragma unroll
            for (int q = 0; q < 4; q++) acc[i][j][q] = 0.f;

    int st_i = 0, ph = 0;
    for (int kt = 0; kt < KT_TOT; kt++) {
        mbar_wait(barb + 16 * st_i, (uint32_t)ph);     // acquire full[s]
        const uint32_t sa = base + st_i * STG;
        const uint32_t sbm = sa + A_STG;

        #pragma unroll
        for (int kk = 0; kk < 64; kk += 16) {
            uint32_t af[2][4];
            #pragma unroll
            for (int mt = 0; mt < 2; mt++) {
                uint32_t p = sa + (wm * 32 + mt * 16 + la) * ROWB + (kk + lb * 8) * 2;
                asm volatile("ldmatrix.sync.aligned.m8n8.x4.shared.b16 {%0,%1,%2,%3},[%4];\n"
                             : "=r"(af[mt][0]), "=r"(af[mt][1]), "=r"(af[mt][2]), "=r"(af[mt][3])
                             : "r"(p));
            }
            uint32_t bf_[2][4];
            #pragma unroll
            for (int nh = 0; nh < 2; nh++) {
                uint32_t p = sbm + (kk + la) * ROWB + (wn * 32 + nh * 16 + lb * 8) * 2;
                asm volatile("ldmatrix.sync.aligned.m8n8.x4.trans.shared.b16 {%0,%1,%2,%3},[%4];\n"
                             : "=r"(bf_[nh][0]), "=r"(bf_[nh][1]), "=r"(bf_[nh][2]), "=r"(bf_[nh][3])
                             : "r"(p));
            }
            #pragma unroll
            for (int mt = 0; mt < 2; mt++)
                #pragma unroll
                for (int nt = 0; nt < 4; nt++) {
                    uint32_t b0 = bf_[nt >> 1][(nt & 1) * 2];
                    uint32_t b1 = bf_[nt >> 1][(nt & 1) * 2 + 1];
                    float* c = acc[mt][nt];
                    asm volatile(
                        "mma.sync.aligned.m16n8k16.row.col.f32.bf16.bf16.f32 "
                        "{%0,%1,%2,%3},{%4,%5,%6,%7},{%8,%9},{%0,%1,%2,%3};\n"
                        : "+f"(c[0]), "+f"(c[1]), "+f"(c[2]), "+f"(c[3])
                        : "r"(af[mt][0]), "r"(af[mt][1]), "r"(af[mt][2]), "r"(af[mt][3]),
                          "r"(b0), "r"(b1));
                }
        }
        mbar_arrive(barb + 16 * st_i + 8);             // release empty[s]
        if (++st_i == STAGES) { st_i = 0; ph ^= 1; }
    }

    // epilogue: S_next[r] = d_r*acc + P[r]; state T_next = bf16(d_r * S_next)
    #pragma unroll
    for (int mt = 0; mt < 2; mt++) {
        const size_t gr0 = b * NN + m0 + wm * 32 + mt * 16 + (lane >> 2);
        const size_t gr1 = gr0 + 8;
        const float d0 = g_deg[gr0], d1 = g_deg[gr1];
        #pragma unroll
        for (int nt = 0; nt < 4; nt++) {
            int c = wn * 32 + nt * 8 + (lane & 3) * 2;
            float2 p0 = *(const float2*)(Padd + gr0 * DIM + c);
            float2 p1 = *(const float2*)(Padd + gr1 * DIM + c);
            float* ac = acc[mt][nt];
            float s00 = d0 * ac[0] + p0.x, s01 = d0 * ac[1] + p0.y;
            float s10 = d1 * ac[2] + p1.x, s11 = d1 * ac[3] + p1.y;
            if (outp) {
                float b0 = bias[c], b1 = bias[c + 1];
                *(float2*)(outp + gr0 * DIM + c) = make_float2(s00 + b0, s01 + b1);
                *(float2*)(outp + gr1 * DIM + c) = make_float2(s10 + b0, s11 + b1);
            } else {
                *(__nv_bfloat162*)(Tout + gr0 * DIM + c) = __floats2bfloat162_rn(d0 * s00, d0 * s01);
                *(__nv_bfloat162*)(Tout + gr1 * DIM + c) = __floats2bfloat162_rn(d1 * s10, d1 * s11);
            }
        }
    }
}

// ---------------- launch ----------------
extern "C" void kernel_launch(void* const* d_in, const int* in_sizes, int n_in,
                              void* d_out, int out_size) {
    const float* x     = (const float*)d_in[0];   // [4,4096,64]
    const float* graph = (const float*)d_in[1];   // [4,4096,4096]
    const float* W     = (const float*)d_in[2];   // [64,256]
    const float* bias  = (const float*)d_in[3];   // [64]
    float* out = (float*)d_out;                   // [4,4096,64]

    const int smem_bytes = STAGES * STG + STAGES * 16;    // 92160 + 80
    static bool attr_set = false;                 // persistent process state, not a work guard
    if (!attr_set) {
        cudaFuncSetAttribute(gemm_kernel, cudaFuncAttributeMaxDynamicSharedMemorySize, smem_bytes);
        attr_set = true;
    }

    prep_kernel<<<NROWS / 8, 256>>>(graph);
    precompute_kernel<<<NROWS / 64, 256>>>(x, W);

    __nv_bfloat16* s0 = nullptr;
    cudaGetSymbolAddress((void**)&s0, g_sbf);     // g_sbf[0]
    __nv_bfloat16* s1 = s0 + (size_t)NROWS * DIM; // g_sbf[1]
    float* P = nullptr;
    cudaGetSymbolAddress((void**)&P, g_P);        // g_P[0]

    dim3 grid(NN / 64, BATCH);                    // 64 x 4 = 256 CTAs
    // step 0: T1 <- d*(d*(A@T0) + P2)
    gemm_kernel<<<grid, 256, smem_bytes>>>(s0, s1, P + 2 * (size_t)NROWS * DIM, nullptr, bias);
    // step 1: T0 <- d*(d*(A@T1) + P1)
    gemm_kernel<<<grid, 256, smem_bytes>>>(s1, s0, P + 1 * (size_t)NROWS * DIM, nullptr, bias);
    // step 2: out = d*(A@T0) + P0 + bias
    gemm_kernel<<<grid, 256, smem_bytes>>>(s0, s1, P, out, bias);
}